// round 1
// baseline (speedup 1.0000x reference)
#include <cuda_runtime.h>
#include <cuda_bf16.h>
#include <cstdint>

#define BATCHN 32
#define SEQ    1024
#define DIM    128
#define KC     32
#define NITER  (SEQ / KC)
#define PK     136   // pitch (elems) for [*][128] bf16 tiles: 272B = 17x16B -> ldmatrix conflict-free
#define PJ     40    // pitch (elems) for self tiles [128][32]: 80B = 5x16B -> conflict-free

// ---------------- PTX helpers ----------------
__device__ __forceinline__ unsigned smaddr(const void* p) {
    return (unsigned)__cvta_generic_to_shared(p);
}
__device__ __forceinline__ void ldsm4(unsigned* r, unsigned a) {
    asm volatile("ldmatrix.sync.aligned.m8n8.x4.shared.b16 {%0,%1,%2,%3},[%4];"
                 : "=r"(r[0]), "=r"(r[1]), "=r"(r[2]), "=r"(r[3]) : "r"(a));
}
__device__ __forceinline__ void ldsm4t(unsigned* r, unsigned a) {
    asm volatile("ldmatrix.sync.aligned.m8n8.x4.trans.shared.b16 {%0,%1,%2,%3},[%4];"
                 : "=r"(r[0]), "=r"(r[1]), "=r"(r[2]), "=r"(r[3]) : "r"(a));
}
__device__ __forceinline__ void mma16816(float* c, const unsigned* a, const unsigned* b) {
    asm volatile("mma.sync.aligned.m16n8k16.row.col.f32.bf16.bf16.f32 "
                 "{%0,%1,%2,%3},{%4,%5,%6,%7},{%8,%9},{%0,%1,%2,%3};"
                 : "+f"(c[0]), "+f"(c[1]), "+f"(c[2]), "+f"(c[3])
                 : "r"(a[0]), "r"(a[1]), "r"(a[2]), "r"(a[3]), "r"(b[0]), "r"(b[1]));
}
// pack two f32 -> bf16x2 (lo in low half)
__device__ __forceinline__ unsigned packbf(float lo, float hi) {
    unsigned r;
    asm("cvt.rn.bf16x2.f32 %0, %1, %2;" : "=r"(r) : "f"(hi), "f"(lo));
    return r;
}
__device__ __forceinline__ float lrelu(float x) { return x >= 0.f ? x : 0.1f * x; }

// ---------------- kernel ----------------
// Grid: (SEQ/128, BATCHN). Block: 256 threads (8 warps, each owns 16 rows of the i-tile).
// Phase 1: P[i,d] = sum_o mask[o,i]*nodes[o,d]  (bf16 MMA, fp32 accum) + counts c[i]
// Phase 2: out = lrelu( (P/max(c,1)) @ W  +  nodes_self @ B )  with split-bf16 for nodes@B
__global__ __launch_bounds__(256, 1)
void gcn_fused_kernel(const float* __restrict__ nodes, const int* __restrict__ adj,
                      const float* __restrict__ Wm, const float* __restrict__ Bm,
                      float* __restrict__ out)
{
    __shared__ __align__(16) unsigned char smem[46592];
    __shared__ int scnt[128];

    const int t    = threadIdx.x;
    const int lane = t & 31;
    const int wid  = t >> 5;
    const int b    = blockIdx.y;
    const int i0   = blockIdx.x * 128;

    if (t < 128) scnt[t] = 0;

    uint16_t* smA = (uint16_t*)smem;                         // mask tile  [KC][PK]
    uint16_t* smN = (uint16_t*)(smem + KC * PK * 2);         // nodes tile [KC][PK]

    // staging coords: thread handles rows o = wid + 8p, cols i = 4*lane..+3
    const int sl = lane;
    const int so = wid;
    const int*   adjBase = adj   + (long long)b * SEQ * SEQ + i0 + 4 * sl;
    const float* nodBase = nodes + (long long)b * SEQ * DIM + 4 * sl;

    float c[64];
#pragma unroll
    for (int i = 0; i < 64; i++) c[i] = 0.f;
    int cnt0 = 0, cnt1 = 0, cnt2 = 0, cnt3 = 0;

    // prefetch iter 0
    int4   mreg[4];
    float4 nreg[4];
#pragma unroll
    for (int p = 0; p < 4; p++) {
        int o = so + 8 * p;
        mreg[p] = *(const int4*)(adjBase + (long long)o * SEQ);
        nreg[p] = *(const float4*)(nodBase + (long long)o * DIM);
    }

    // ldmatrix smem base offsets (bytes)
    // A (trans, A = mask^T): row = (l&7) + ((l>>4)&1)*8 ; col = wid*16 + ((l>>3)&1)*8
    const unsigned aRow = (lane & 7) + ((lane >> 4) & 1) * 8;
    const unsigned aCol = wid * 16 + ((lane >> 3) & 1) * 8;
    const unsigned smA_base = smaddr(smA) + (aRow * PK + aCol) * 2;
    // B (trans, B = [k][n] row-major): row = (l&7) + ((l>>3)&1)*8 ; col = ((l>>4)&1)*8 (+16*nb)
    const unsigned bRow = (lane & 7) + ((lane >> 3) & 1) * 8;
    const unsigned bCol = ((lane >> 4) & 1) * 8;
    const unsigned smN_base = smaddr(smN) + (bRow * PK + bCol) * 2;

    for (int it = 0; it < NITER; ++it) {
        // convert + store current regs to smem, accumulate counts
#pragma unroll
        for (int p = 0; p < 4; p++) {
            int o = so + 8 * p;
            int4 m = mreg[p];
            cnt0 += (m.x != 0); cnt1 += (m.y != 0); cnt2 += (m.z != 0); cnt3 += (m.w != 0);
            unsigned lo = (m.x ? 0x3F80u : 0u) | (m.y ? 0x3F800000u : 0u);
            unsigned hi = (m.z ? 0x3F80u : 0u) | (m.w ? 0x3F800000u : 0u);
            *(uint2*)(smA + o * PK + 4 * sl) = make_uint2(lo, hi);
            float4 n = nreg[p];
            *(uint2*)(smN + o * PK + 4 * sl) = make_uint2(packbf(n.x, n.y), packbf(n.z, n.w));
        }
        // prefetch next tile (overlaps with MMA below)
        if (it + 1 < NITER) {
            const int*   ab = adjBase + (long long)(it + 1) * KC * SEQ;
            const float* nb = nodBase + (long long)(it + 1) * KC * DIM;
#pragma unroll
            for (int p = 0; p < 4; p++) {
                int o = so + 8 * p;
                mreg[p] = *(const int4*)(ab + (long long)o * SEQ);
                nreg[p] = *(const float4*)(nb + (long long)o * DIM);
            }
        }
        __syncthreads();
        // consume: 2 k-steps of 16, N=128 (16 n8-tiles)
#pragma unroll
        for (int kk = 0; kk < 2; kk++) {
            unsigned a[4];
            ldsm4t(a, smA_base + kk * 16 * PK * 2);
#pragma unroll
            for (int nb = 0; nb < 8; nb++) {
                unsigned bb[4];
                ldsm4t(bb, smN_base + (kk * 16 * PK + nb * 16) * 2);
                mma16816(c + 4 * (2 * nb + 0), a, bb);
                mma16816(c + 4 * (2 * nb + 1), a, bb + 2);
            }
        }
        __syncthreads();
    }

    // finalize counts
    atomicAdd(&scnt[4 * sl + 0], cnt0);
    atomicAdd(&scnt[4 * sl + 1], cnt1);
    atomicAdd(&scnt[4 * sl + 2], cnt2);
    atomicAdd(&scnt[4 * sl + 3], cnt3);
    __syncthreads();

    // scale by 1/max(c,1) and pack P into bf16 A-fragments (C->A register reuse)
    const int r0 = wid * 16 + (lane >> 2);
    const float inv0 = 1.f / fmaxf((float)scnt[r0], 1.f);
    const float inv1 = 1.f / fmaxf((float)scnt[r0 + 8], 1.f);
    unsigned pA[32];
#pragma unroll
    for (int nt = 0; nt < 16; nt++) {
        pA[2 * nt + 0] = packbf(c[4 * nt + 0] * inv0, c[4 * nt + 1] * inv0);
        pA[2 * nt + 1] = packbf(c[4 * nt + 2] * inv1, c[4 * nt + 3] * inv1);
    }

    // ---- stage 2: out = P@W + selfH@Bh + selfH@Bl + selfL@Bh ----
    uint16_t* sW  = (uint16_t*)smem;            // [KC][PK]
    uint16_t* sBh = sW  + KC * PK;
    uint16_t* sBl = sBh + KC * PK;
    uint16_t* sSh = sBl + KC * PK;              // [128][PJ]
    uint16_t* sSl = sSh + 128 * PJ;

    float c2[64];
#pragma unroll
    for (int i = 0; i < 64; i++) c2[i] = 0.f;

    // A (non-trans) from self tiles: row = wid*16 + (l&15); col = (l>>4)*8 (+16*jj)
    const unsigned aS_off = ((wid * 16 + (lane & 15)) * PJ + ((lane >> 4) & 1) * 8) * 2;
    const unsigned bW_off = (bRow * PK + bCol) * 2;

#pragma unroll
    for (int jc = 0; jc < 4; ++jc) {
        __syncthreads();   // prior consumers done with smem
        const int j0 = jc * 32;
        // stage W / B(hi,lo) slices [32 j][128 d]
#pragma unroll
        for (int p = 0; p < 4; p++) {
            int jr = so + 8 * p;
            float4 w = *(const float4*)(Wm + (j0 + jr) * DIM + 4 * sl);
            *(uint2*)(sW + jr * PK + 4 * sl) = make_uint2(packbf(w.x, w.y), packbf(w.z, w.w));
            float4 bm = *(const float4*)(Bm + (j0 + jr) * DIM + 4 * sl);
            float hx = __bfloat162float(__float2bfloat16_rn(bm.x));
            float hy = __bfloat162float(__float2bfloat16_rn(bm.y));
            float hz = __bfloat162float(__float2bfloat16_rn(bm.z));
            float hw = __bfloat162float(__float2bfloat16_rn(bm.w));
            *(uint2*)(sBh + jr * PK + 4 * sl) = make_uint2(packbf(hx, hy), packbf(hz, hw));
            *(uint2*)(sBl + jr * PK + 4 * sl) =
                make_uint2(packbf(bm.x - hx, bm.y - hy), packbf(bm.z - hz, bm.w - hw));
        }
        // stage self-nodes slice [128 i][32 j], hi/lo split
#pragma unroll
        for (int p = 0; p < 4; p++) {
            int q  = t + 256 * p;
            int rr = q >> 3;
            int jg = (q & 7) * 4;
            float4 v = *(const float4*)(nodes + ((long long)b * SEQ + i0 + rr) * DIM + j0 + jg);
            float hx = __bfloat162float(__float2bfloat16_rn(v.x));
            float hy = __bfloat162float(__float2bfloat16_rn(v.y));
            float hz = __bfloat162float(__float2bfloat16_rn(v.z));
            float hw = __bfloat162float(__float2bfloat16_rn(v.w));
            *(uint2*)(sSh + rr * PJ + jg) = make_uint2(packbf(hx, hy), packbf(hz, hw));
            *(uint2*)(sSl + rr * PJ + jg) =
                make_uint2(packbf(v.x - hx, v.y - hy), packbf(v.z - hz, v.w - hw));
        }
        __syncthreads();
#pragma unroll
        for (int jj = 0; jj < 2; jj++) {
            unsigned aH[4], aL[4];
            ldsm4(aH, smaddr(sSh) + aS_off + jj * 16 * 2);
            ldsm4(aL, smaddr(sSl) + aS_off + jj * 16 * 2);
            const unsigned* aP = pA + (jc * 2 + jj) * 4;
#pragma unroll
            for (int nb = 0; nb < 8; nb++) {
                const unsigned off = (jj * 16 * PK + nb * 16) * 2;
                unsigned bW[4], bH[4], bL[4];
                ldsm4t(bW, smaddr(sW)  + bW_off + off);
                ldsm4t(bH, smaddr(sBh) + bW_off + off);
                ldsm4t(bL, smaddr(sBl) + bW_off + off);
                float* cc0 = c2 + 8 * nb;
                float* cc1 = c2 + 8 * nb + 4;
                mma16816(cc0, aP, bW);  mma16816(cc1, aP, bW + 2);
                mma16816(cc0, aH, bH);  mma16816(cc1, aH, bH + 2);
                mma16816(cc0, aH, bL);  mma16816(cc1, aH, bL + 2);
                mma16816(cc0, aL, bH);  mma16816(cc1, aL, bH + 2);
            }
        }
    }

    // epilogue: leaky relu + store
    const int orow = i0 + wid * 16 + (lane >> 2);
    const int ocol = 2 * (lane & 3);
    float* outB = out + ((long long)b * SEQ + orow) * DIM;
#pragma unroll
    for (int nt = 0; nt < 16; nt++) {
        int colx = 8 * nt + ocol;
        float2 v01 = make_float2(lrelu(c2[4 * nt + 0]), lrelu(c2[4 * nt + 1]));
        float2 v23 = make_float2(lrelu(c2[4 * nt + 2]), lrelu(c2[4 * nt + 3]));
        *(float2*)(outB + colx)            = v01;
        *(float2*)(outB + 8 * DIM + colx)  = v23;
    }
}

extern "C" void kernel_launch(void* const* d_in, const int* in_sizes, int n_in,
                              void* d_out, int out_size)
{
    const float* nodes = (const float*)d_in[0];
    const int*   adj   = (const int*)d_in[1];
    const float* Wm    = (const float*)d_in[2];
    const float* Bm    = (const float*)d_in[3];
    float*       out   = (float*)d_out;

    dim3 grid(SEQ / 128, BATCHN);
    gcn_fused_kernel<<<grid, 256>>>(nodes, adj, Wm, Bm, out);
}

// round 3
// speedup vs baseline: 1.4739x; 1.4739x over previous
#include <cuda_runtime.h>
#include <cuda_bf16.h>
#include <cstdint>

#define BATCHN 32
#define SEQ    1024
#define DIM    128
#define KC     32
#define NITER  (SEQ / KC)
#define PK     136
#define PJ     40

__device__ uint4 g_nbf4[BATCHN * SEQ * DIM / 8];
__device__ uint4 g_nlo4[BATCHN * SEQ * DIM / 8];
__device__ uint4 g_wbf4[DIM * DIM / 8];
__device__ uint4 g_bh4[DIM * DIM / 8];
__device__ uint4 g_bl4[DIM * DIM / 8];

__device__ __forceinline__ unsigned smaddr(const void* p) {
    return (unsigned)__cvta_generic_to_shared(p);
}
__device__ __forceinline__ void ldsm4(unsigned* r, unsigned a) {
    asm volatile("ldmatrix.sync.aligned.m8n8.x4.shared.b16 {%0,%1,%2,%3},[%4];"
                 : "=r"(r[0]), "=r"(r[1]), "=r"(r[2]), "=r"(r[3]) : "r"(a));
}
__device__ __forceinline__ void ldsm4t(unsigned* r, unsigned a) {
    asm volatile("ldmatrix.sync.aligned.m8n8.x4.trans.shared.b16 {%0,%1,%2,%3},[%4];"
                 : "=r"(r[0]), "=r"(r[1]), "=r"(r[2]), "=r"(r[3]) : "r"(a));
}
__device__ __forceinline__ void mma16816(float* c, const unsigned* a, const unsigned* b) {
    asm volatile("mma.sync.aligned.m16n8k16.row.col.f32.bf16.bf16.f32 "
                 "{%0,%1,%2,%3},{%4,%5,%6,%7},{%8,%9},{%0,%1,%2,%3};"
                 : "+f"(c[0]), "+f"(c[1]), "+f"(c[2]), "+f"(c[3])
                 : "r"(a[0]), "r"(a[1]), "r"(a[2]), "r"(a[3]), "r"(b[0]), "r"(b[1]));
}
__device__ __forceinline__ unsigned packbf(float lo, float hi) {
    unsigned r;
    asm("cvt.rn.bf16x2.f32 %0, %1, %2;" : "=r"(r) : "f"(hi), "f"(lo));
    return r;
}
__device__ __forceinline__ void cpa16(unsigned s, const void* g) {
    asm volatile("cp.async.cg.shared.global [%0], [%1], 16;" :: "r"(s), "l"(g) : "memory");
}
__device__ __forceinline__ void cp_commit() {
    asm volatile("cp.async.commit_group;" ::: "memory");
}
__device__ __forceinline__ float lrelu(float x) { return x >= 0.f ? x : 0.1f * x; }

__global__ void prep_nodes(const float* __restrict__ nodes) {
    long long i = ((long long)blockIdx.x * 256 + threadIdx.x) * 4;
    float4 v = *(const float4*)(nodes + i);
    float hx = __bfloat162float(__float2bfloat16_rn(v.x));
    float hy = __bfloat162float(__float2bfloat16_rn(v.y));
    float hz = __bfloat162float(__float2bfloat16_rn(v.z));
    float hw = __bfloat162float(__float2bfloat16_rn(v.w));
    *(uint2*)((__nv_bfloat16*)g_nbf4 + i) = make_uint2(packbf(hx, hy), packbf(hz, hw));
    *(uint2*)((__nv_bfloat16*)g_nlo4 + i) =
        make_uint2(packbf(v.x - hx, v.y - hy), packbf(v.z - hz, v.w - hw));
}

__global__ void prep_params(const float* __restrict__ Wm, const float* __restrict__ Bm) {
    int q = blockIdx.x * 256 + threadIdx.x;
    if (q < 4096) {
        long long i = (long long)q * 4;
        float4 w = *(const float4*)(Wm + i);
        *(uint2*)((__nv_bfloat16*)g_wbf4 + i) = make_uint2(packbf(w.x, w.y), packbf(w.z, w.w));
    } else {
        long long i = (long long)(q - 4096) * 4;
        float4 v = *(const float4*)(Bm + i);
        float hx = __bfloat162float(__float2bfloat16_rn(v.x));
        float hy = __bfloat162float(__float2bfloat16_rn(v.y));
        float hz = __bfloat162float(__float2bfloat16_rn(v.z));
        float hw = __bfloat162float(__float2bfloat16_rn(v.w));
        *(uint2*)((__nv_bfloat16*)g_bh4 + i) = make_uint2(packbf(hx, hy), packbf(hz, hw));
        *(uint2*)((__nv_bfloat16*)g_bl4 + i) =
            make_uint2(packbf(v.x - hx, v.y - hy), packbf(v.z - hz, v.w - hw));
    }
}

#define OFF_NODE 17408
#define OFF_P    52224
#define OFF_W    0
#define OFF_BH   8704
#define OFF_BL   17408
#define OFF_SH   26112
#define OFF_SL   36352
#define SMEM_SZ  87040

__global__ __launch_bounds__(256, 2)
void gcn_fused_kernel(const int* __restrict__ adj, float* __restrict__ out)
{
    extern __shared__ __align__(16) unsigned char smem[];
    __shared__ int scnt[128];

    const int t    = threadIdx.x;
    const int lane = t & 31;
    const int wid  = t >> 5;
    const int b    = blockIdx.y;
    const int i0   = blockIdx.x * 128;

    if (t < 128) scnt[t] = 0;

    const int* adjBase = adj + (long long)b * SEQ * SEQ + i0 + 4 * lane;
    const __nv_bfloat16* nbfB = (const __nv_bfloat16*)g_nbf4 + (long long)b * SEQ * DIM;
    const __nv_bfloat16* nloB = (const __nv_bfloat16*)g_nlo4 + (long long)b * SEQ * DIM;

    const int ncRow0 = t >> 4,         ncCol0 = t & 15;
    const int ncRow1 = (t + 256) >> 4, ncCol1 = (t + 256) & 15;
    const unsigned nodeSm = smaddr(smem + OFF_NODE);

#define ISSUE_NODES(IT) do {                                                      \
        unsigned _sb = nodeSm + ((IT) & 3) * 8704;                                \
        const __nv_bfloat16* _g = nbfB + (IT) * KC * DIM;                         \
        cpa16(_sb + ncRow0 * 272 + ncCol0 * 16, _g + ncRow0 * DIM + ncCol0 * 8);  \
        cpa16(_sb + ncRow1 * 272 + ncCol1 * 16, _g + ncRow1 * DIM + ncCol1 * 8);  \
        cp_commit();                                                              \
    } while (0)

    ISSUE_NODES(0);
    ISSUE_NODES(1);

    int4 mreg[4];
#pragma unroll
    for (int p = 0; p < 4; p++)
        mreg[p] = *(const int4*)(adjBase + (long long)(wid + 8 * p) * SEQ);

    float c[64];
#pragma unroll
    for (int i = 0; i < 64; i++) c[i] = 0.f;
    int cnt0 = 0, cnt1 = 0, cnt2 = 0, cnt3 = 0;

    const unsigned aRow = (lane & 7) + ((lane >> 4) & 1) * 8;
    const unsigned aCol = wid * 16 + ((lane >> 3) & 1) * 8;
    const unsigned aOff = (aRow * PK + aCol) * 2;
    const unsigned bRow = (lane & 7) + ((lane >> 3) & 1) * 8;
    const unsigned bCol = ((lane >> 4) & 1) * 8;
    const unsigned bOff = (bRow * PK + bCol) * 2;
    const unsigned maskSm = smaddr(smem);

    for (int it = 0; it < NITER; ++it) {
        unsigned mst = (it & 1) * 8704;
#pragma unroll
        for (int p = 0; p < 4; p++) {
            int o = wid + 8 * p;
            int4 m = mreg[p];
            cnt0 += (m.x != 0); cnt1 += (m.y != 0); cnt2 += (m.z != 0); cnt3 += (m.w != 0);
            unsigned lo = (m.x ? 0x3F80u : 0u) | (m.y ? 0x3F800000u : 0u);
            unsigned hi = (m.z ? 0x3F80u : 0u) | (m.w ? 0x3F800000u : 0u);
            *(uint2*)(smem + mst + (o * PK + 4 * lane) * 2) = make_uint2(lo, hi);
        }
        if (it + 1 < NITER) {
            const int* ab = adjBase + (long long)(it + 1) * KC * SEQ;
#pragma unroll
            for (int p = 0; p < 4; p++)
                mreg[p] = *(const int4*)(ab + (long long)(wid + 8 * p) * SEQ);
        }
        {
            int nx = it + 2;
            if (nx >= NITER) nx -= NITER;   // tail wrap: stage never consumed again
            ISSUE_NODES(nx);
        }
        asm volatile("cp.async.wait_group 2;" ::: "memory");
        __syncthreads();

        const unsigned mA = maskSm + (it & 1) * 8704 + aOff;
        const unsigned nB = nodeSm + (it & 3) * 8704 + bOff;
#pragma unroll
        for (int kk = 0; kk < 2; kk++) {
            unsigned a[4];
            ldsm4t(a, mA + kk * 16 * PK * 2);
#pragma unroll
            for (int nb = 0; nb < 8; nb++) {
                unsigned bb[4];
                ldsm4t(bb, nB + (kk * 16 * PK + nb * 16) * 2);
                mma16816(c + 4 * (2 * nb + 0), a, bb);
                mma16816(c + 4 * (2 * nb + 1), a, bb + 2);
            }
        }
    }

    atomicAdd(&scnt[4 * lane + 0], cnt0);
    atomicAdd(&scnt[4 * lane + 1], cnt1);
    atomicAdd(&scnt[4 * lane + 2], cnt2);
    atomicAdd(&scnt[4 * lane + 3], cnt3);
    __syncthreads();

    const int r0 = wid * 16 + (lane >> 2);
    const float inv0 = 1.f / fmaxf((float)scnt[r0], 1.f);
    const float inv1 = 1.f / fmaxf((float)scnt[r0 + 8], 1.f);
    {
        unsigned char* P = smem + OFF_P;
        const int cb = 2 * (lane & 3);
#pragma unroll
        for (int nt = 0; nt < 16; nt++) {
            *(unsigned*)(P + (r0 * PK + 8 * nt + cb) * 2) =
                packbf(c[4 * nt + 0] * inv0, c[4 * nt + 1] * inv0);
            *(unsigned*)(P + ((r0 + 8) * PK + 8 * nt + cb) * 2) =
                packbf(c[4 * nt + 2] * inv1, c[4 * nt + 3] * inv1);
        }
    }
    __syncthreads();

    // ---- phase 2 ----
#pragma unroll
    for (int i = 0; i < 64; i++) c[i] = 0.f;

    const int sRow0 = t >> 2,         sCol0 = t & 3;
    const int sRow1 = (t + 256) >> 2, sCol1 = (t + 256) & 3;
    const unsigned aS_base = ((wid * 16 + (lane & 15)) * PJ + ((lane >> 4) & 1) * 8) * 2;
    const unsigned aP_base = ((wid * 16 + (lane & 15)) * PK + ((lane >> 4) & 1) * 8) * 2;
    const __nv_bfloat16* wbf = (const __nv_bfloat16*)g_wbf4;
    const __nv_bfloat16* bhp = (const __nv_bfloat16*)g_bh4;
    const __nv_bfloat16* blp = (const __nv_bfloat16*)g_bl4;

#pragma unroll 1
    for (int jc = 0; jc < 4; ++jc) {
        const int d0 = jc * 32;
        {
            int go0 = (d0 + ncRow0) * DIM + ncCol0 * 8;
            int go1 = (d0 + ncRow1) * DIM + ncCol1 * 8;
            unsigned so0 = ncRow0 * 272 + ncCol0 * 16;
            unsigned so1 = ncRow1 * 272 + ncCol1 * 16;
            cpa16(smaddr(smem + OFF_W)  + so0, wbf + go0);
            cpa16(smaddr(smem + OFF_W)  + so1, wbf + go1);
            cpa16(smaddr(smem + OFF_BH) + so0, bhp + go0);
            cpa16(smaddr(smem + OFF_BH) + so1, bhp + go1);
            cpa16(smaddr(smem + OFF_BL) + so0, blp + go0);
            cpa16(smaddr(smem + OFF_BL) + so1, blp + go1);
        }
        {
            long long go0 = (long long)(i0 + sRow0) * DIM + d0 + sCol0 * 8;
            long long go1 = (long long)(i0 + sRow1) * DIM + d0 + sCol1 * 8;
            unsigned so0 = sRow0 * 80 + sCol0 * 16;
            unsigned so1 = sRow1 * 80 + sCol1 * 16;
            cpa16(smaddr(smem + OFF_SH) + so0, nbfB + go0);
            cpa16(smaddr(smem + OFF_SH) + so1, nbfB + go1);
            cpa16(smaddr(smem + OFF_SL) + so0, nloB + go0);
            cpa16(smaddr(smem + OFF_SL) + so1, nloB + go1);
        }
        cp_commit();
        asm volatile("cp.async.wait_group 0;" ::: "memory");
        __syncthreads();

#pragma unroll
        for (int jj = 0; jj < 2; jj++) {
            unsigned aH[4], aL[4], aP[4];
            ldsm4(aH, smaddr(smem + OFF_SH) + aS_base + jj * 16 * 2);
            ldsm4(aL, smaddr(smem + OFF_SL) + aS_base + jj * 16 * 2);
            ldsm4(aP, smaddr(smem + OFF_P) + aP_base + (d0 + jj * 16) * 2);
#pragma unroll
            for (int nb = 0; nb < 8; nb++) {
                const unsigned off = bOff + (jj * 16 * PK + nb * 16) * 2;
                unsigned bW[4], bH[4], bL[4];
                ldsm4t(bW, smaddr(smem + OFF_W)  + off);
                ldsm4t(bH, smaddr(smem + OFF_BH) + off);
                ldsm4t(bL, smaddr(smem + OFF_BL) + off);
                float* cc0 = c + 8 * nb;
                float* cc1 = c + 8 * nb + 4;
                mma16816(cc0, aP, bW);  mma16816(cc1, aP, bW + 2);
                mma16816(cc0, aH, bH);  mma16816(cc1, aH, bH + 2);
                mma16816(cc0, aH, bL);  mma16816(cc1, aH, bL + 2);
                mma16816(cc0, aL, bH);  mma16816(cc1, aL, bH + 2);
            }
        }
        __syncthreads();
    }

    const int orow = i0 + wid * 16 + (lane >> 2);
    const int ocol = 2 * (lane & 3);
    float* outB = out + ((long long)b * SEQ + orow) * DIM;
#pragma unroll
    for (int nt = 0; nt < 16; nt++) {
        int colx = 8 * nt + ocol;
        float2 v01 = make_float2(lrelu(c[4 * nt + 0]), lrelu(c[4 * nt + 1]));
        float2 v23 = make_float2(lrelu(c[4 * nt + 2]), lrelu(c[4 * nt + 3]));
        *(float2*)(outB + colx)           = v01;
        *(float2*)(outB + 8 * DIM + colx) = v23;
    }
}

extern "C" void kernel_launch(void* const* d_in, const int* in_sizes, int n_in,
                              void* d_out, int out_size)
{
    (void)in_sizes; (void)n_in; (void)out_size;
    const float* nodes = (const float*)d_in[0];
    const int*   adj   = (const int*)d_in[1];
    const float* Wm    = (const float*)d_in[2];
    const float* Bm    = (const float*)d_in[3];
    float*       out   = (float*)d_out;

    cudaFuncSetAttribute(gcn_fused_kernel,
                         cudaFuncAttributeMaxDynamicSharedMemorySize, SMEM_SZ);

    prep_nodes<<<BATCHN * SEQ * DIM / (256 * 4), 256>>>(nodes);
    prep_params<<<32, 256>>>(Wm, Bm);
    dim3 grid(SEQ / 128, BATCHN);
    gcn_fused_kernel<<<grid, 256, SMEM_SZ>>>(adj, out);
}

// round 6
// speedup vs baseline: 1.4848x; 1.0074x over previous
#include <cuda_runtime.h>
#include <cuda_bf16.h>
#include <cstdint>

#define BATCHN 32
#define SEQ    1024
#define DIM    128
#define KC     32
#define NITER  (SEQ / KC)
#define PK     136
#define PJ2    24        // self-chunk row pitch (elems): 48B, conflict-free for ldsm x4

__device__ uint4 g_nbf4[BATCHN * SEQ * DIM / 8];
__device__ uint4 g_nlo4[BATCHN * SEQ * DIM / 8];
__device__ uint4 g_wbf4[DIM * DIM / 8];
__device__ uint4 g_bh4[DIM * DIM / 8];
__device__ uint4 g_bl4[DIM * DIM / 8];

__device__ __forceinline__ unsigned smaddr(const void* p) {
    return (unsigned)__cvta_generic_to_shared(p);
}
__device__ __forceinline__ void ldsm4(unsigned* r, unsigned a) {
    asm volatile("ldmatrix.sync.aligned.m8n8.x4.shared.b16 {%0,%1,%2,%3},[%4];"
                 : "=r"(r[0]), "=r"(r[1]), "=r"(r[2]), "=r"(r[3]) : "r"(a));
}
__device__ __forceinline__ void ldsm4t(unsigned* r, unsigned a) {
    asm volatile("ldmatrix.sync.aligned.m8n8.x4.trans.shared.b16 {%0,%1,%2,%3},[%4];"
                 : "=r"(r[0]), "=r"(r[1]), "=r"(r[2]), "=r"(r[3]) : "r"(a));
}
__device__ __forceinline__ void mma16816(float* c, const unsigned* a, const unsigned* b) {
    asm volatile("mma.sync.aligned.m16n8k16.row.col.f32.bf16.bf16.f32 "
                 "{%0,%1,%2,%3},{%4,%5,%6,%7},{%8,%9},{%0,%1,%2,%3};"
                 : "+f"(c[0]), "+f"(c[1]), "+f"(c[2]), "+f"(c[3])
                 : "r"(a[0]), "r"(a[1]), "r"(a[2]), "r"(a[3]), "r"(b[0]), "r"(b[1]));
}
__device__ __forceinline__ unsigned packbf(float lo, float hi) {
    unsigned r;
    asm("cvt.rn.bf16x2.f32 %0, %1, %2;" : "=r"(r) : "f"(hi), "f"(lo));
    return r;
}
__device__ __forceinline__ void cpa16(unsigned s, const void* g) {
    asm volatile("cp.async.cg.shared.global [%0], [%1], 16;" :: "r"(s), "l"(g) : "memory");
}
__device__ __forceinline__ void cp_commit() {
    asm volatile("cp.async.commit_group;" ::: "memory");
}
__device__ __forceinline__ float lrelu(float x) { return x >= 0.f ? x : 0.1f * x; }

__global__ void prep_nodes(const float* __restrict__ nodes) {
    long long i = ((long long)blockIdx.x * 256 + threadIdx.x) * 4;
    float4 v = *(const float4*)(nodes + i);
    float hx = __bfloat162float(__float2bfloat16_rn(v.x));
    float hy = __bfloat162float(__float2bfloat16_rn(v.y));
    float hz = __bfloat162float(__float2bfloat16_rn(v.z));
    float hw = __bfloat162float(__float2bfloat16_rn(v.w));
    *(uint2*)((__nv_bfloat16*)g_nbf4 + i) = make_uint2(packbf(hx, hy), packbf(hz, hw));
    *(uint2*)((__nv_bfloat16*)g_nlo4 + i) =
        make_uint2(packbf(v.x - hx, v.y - hy), packbf(v.z - hz, v.w - hw));
}

__global__ void prep_params(const float* __restrict__ Wm, const float* __restrict__ Bm) {
    int q = blockIdx.x * 256 + threadIdx.x;
    if (q < 4096) {
        long long i = (long long)q * 4;
        float4 w = *(const float4*)(Wm + i);
        *(uint2*)((__nv_bfloat16*)g_wbf4 + i) = make_uint2(packbf(w.x, w.y), packbf(w.z, w.w));
    } else {
        long long i = (long long)(q - 4096) * 4;
        float4 v = *(const float4*)(Bm + i);
        float hx = __bfloat162float(__float2bfloat16_rn(v.x));
        float hy = __bfloat162float(__float2bfloat16_rn(v.y));
        float hz = __bfloat162float(__float2bfloat16_rn(v.z));
        float hw = __bfloat162float(__float2bfloat16_rn(v.w));
        *(uint2*)((__nv_bfloat16*)g_bh4 + i) = make_uint2(packbf(hx, hy), packbf(hz, hw));
        *(uint2*)((__nv_bfloat16*)g_bl4 + i) =
            make_uint2(packbf(v.x - hx, v.y - hy), packbf(v.z - hz, v.w - hw));
    }
}

// smem map (bytes):
//  phase1: mask 2 stages @0 (17408) + nodes 4 stages @17408 (34816)  -> [0, 52224)
//  P (bf16 normalized)   @52224 (34816)                              -> [52224, 87040)
//  phase2: 2 chunk stages @0, each 25344:
//     W@0(4352) Bh@4352 Bl@8704 SH@13056(6144) SL@19200(6144)        -> [0, 50688)
#define OFF_NODE 17408
#define OFF_P    52224
#define STGSZ    25344
#define C_W      0
#define C_BH     4352
#define C_BL     8704
#define C_SH     13056
#define C_SL     19200
#define CH       16
#define NCH      8
#define SMEM_SZ  87040

__global__ __launch_bounds__(256, 2)
void gcn_fused_kernel(const int* __restrict__ adj, float* __restrict__ out)
{
    extern __shared__ __align__(16) unsigned char smem[];
    __shared__ int scnt[128];

    const int t    = threadIdx.x;
    const int lane = t & 31;
    const int wid  = t >> 5;
    const int b    = blockIdx.y;
    const int i0   = blockIdx.x * 128;

    if (t < 128) scnt[t] = 0;

    const int* adjBase = adj + (long long)b * SEQ * SEQ + i0 + 4 * lane;
    const __nv_bfloat16* nbfB = (const __nv_bfloat16*)g_nbf4 + (long long)b * SEQ * DIM;
    const __nv_bfloat16* nloB = (const __nv_bfloat16*)g_nlo4 + (long long)b * SEQ * DIM;
    const __nv_bfloat16* wbf  = (const __nv_bfloat16*)g_wbf4;
    const __nv_bfloat16* bhp  = (const __nv_bfloat16*)g_bh4;
    const __nv_bfloat16* blp  = (const __nv_bfloat16*)g_bl4;

    const int ncRow0 = t >> 4,         ncCol0 = t & 15;
    const int ncRow1 = (t + 256) >> 4, ncCol1 = (t + 256) & 15;
    const unsigned nodeSm = smaddr(smem + OFF_NODE);

#define ISSUE_NODES(IT) do {                                                      \
        unsigned _sb = nodeSm + ((IT) & 3) * 8704;                                \
        const __nv_bfloat16* _g = nbfB + (IT) * KC * DIM;                         \
        cpa16(_sb + ncRow0 * 272 + ncCol0 * 16, _g + ncRow0 * DIM + ncCol0 * 8);  \
        cpa16(_sb + ncRow1 * 272 + ncCol1 * 16, _g + ncRow1 * DIM + ncCol1 * 8);  \
        cp_commit();                                                              \
    } while (0)

    // phase-2 chunk staging: W/Bh/Bl [16 d][128 j], self hi/lo [128 i][16 d]
#define ISSUE_CHUNK(JC) do {                                                      \
        unsigned _st = smaddr(smem) + ((JC) & 1) * STGSZ;                         \
        const int _d0 = (JC) * CH;                                                \
        {                                                                         \
            int _r = t >> 4, _cc = t & 15;                                        \
            unsigned _so = _r * 272 + _cc * 16;                                   \
            int _go = (_d0 + _r) * DIM + _cc * 8;                                 \
            cpa16(_st + C_W  + _so, wbf + _go);                                   \
            cpa16(_st + C_BH + _so, bhp + _go);                                   \
            cpa16(_st + C_BL + _so, blp + _go);                                   \
        }                                                                         \
        {                                                                         \
            int _r = t >> 1, _cc = t & 1;                                         \
            unsigned _so = _r * 48 + _cc * 16;                                    \
            long long _go = (long long)(i0 + _r) * DIM + _d0 + _cc * 8;           \
            cpa16(_st + C_SH + _so, nbfB + _go);                                  \
            cpa16(_st + C_SL + _so, nloB + _go);                                  \
        }                                                                         \
        cp_commit();                                                              \
    } while (0)

    ISSUE_NODES(0);
    ISSUE_NODES(1);

    int4 mreg[4];
#pragma unroll
    for (int p = 0; p < 4; p++)
        mreg[p] = *(const int4*)(adjBase + (long long)(wid + 8 * p) * SEQ);

    float c[64];
#pragma unroll
    for (int i = 0; i < 64; i++) c[i] = 0.f;
    int cnt0 = 0, cnt1 = 0, cnt2 = 0, cnt3 = 0;

    const unsigned aRow = (lane & 7) + ((lane >> 4) & 1) * 8;
    const unsigned aCol = wid * 16 + ((lane >> 3) & 1) * 8;
    const unsigned aOff = (aRow * PK + aCol) * 2;
    const unsigned bRow = (lane & 7) + ((lane >> 3) & 1) * 8;
    const unsigned bCol = ((lane >> 4) & 1) * 8;
    const unsigned bOff = (bRow * PK + bCol) * 2;
    const unsigned maskSm = smaddr(smem);

    for (int it = 0; it < NITER; ++it) {
        unsigned mst = (it & 1) * 8704;
#pragma unroll
        for (int p = 0; p < 4; p++) {
            int o = wid + 8 * p;
            int4 m = mreg[p];
            cnt0 += (m.x != 0); cnt1 += (m.y != 0); cnt2 += (m.z != 0); cnt3 += (m.w != 0);
            unsigned lo = (m.x ? 0x3F80u : 0u) | (m.y ? 0x3F800000u : 0u);
            unsigned hi = (m.z ? 0x3F80u : 0u) | (m.w ? 0x3F800000u : 0u);
            *(uint2*)(smem + mst + (o * PK + 4 * lane) * 2) = make_uint2(lo, hi);
        }
        if (it + 1 < NITER) {
            const int* ab = adjBase + (long long)(it + 1) * KC * SEQ;
#pragma unroll
            for (int p = 0; p < 4; p++)
                mreg[p] = *(const int4*)(ab + (long long)(wid + 8 * p) * SEQ);
        }
        {
            int nx = it + 2;
            if (nx >= NITER) nx -= NITER;   // tail wrap keeps group FIFO depth uniform
            ISSUE_NODES(nx);
        }
        asm volatile("cp.async.wait_group 2;" ::: "memory");
        __syncthreads();

        const unsigned mA = maskSm + (it & 1) * 8704 + aOff;
        const unsigned nB = nodeSm + (it & 3) * 8704 + bOff;
#pragma unroll
        for (int kk = 0; kk < 2; kk++) {
            unsigned a[4];
            ldsm4t(a, mA + kk * 16 * PK * 2);
#pragma unroll
            for (int nb = 0; nb < 8; nb++) {
                unsigned bb[4];
                ldsm4t(bb, nB + (kk * 16 * PK + nb * 16) * 2);
                mma16816(c + 4 * (2 * nb + 0), a, bb);
                mma16816(c + 4 * (2 * nb + 1), a, bb + 2);
            }
        }
    }

    atomicAdd(&scnt[4 * lane + 0], cnt0);
    atomicAdd(&scnt[4 * lane + 1], cnt1);
    atomicAdd(&scnt[4 * lane + 2], cnt2);
    atomicAdd(&scnt[4 * lane + 3], cnt3);
    // drain stale wrapped node groups: chunk stages reuse their smem region and
    // cross-thread cp.async ordering is not guaranteed
    asm volatile("cp.async.wait_group 0;" ::: "memory");
    __syncthreads();

    // start phase-2 pipeline NOW — loads overlap P normalize/store below
    ISSUE_CHUNK(0);
    ISSUE_CHUNK(1);

    const int r0 = wid * 16 + (lane >> 2);
    const float inv0 = 1.f / fmaxf((float)scnt[r0], 1.f);
    const float inv1 = 1.f / fmaxf((float)scnt[r0 + 8], 1.f);
    {
        unsigned char* P = smem + OFF_P;
        const int cb = 2 * (lane & 3);
#pragma unroll
        for (int nt = 0; nt < 16; nt++) {
            *(unsigned*)(P + (r0 * PK + 8 * nt + cb) * 2) =
                packbf(c[4 * nt + 0] * inv0, c[4 * nt + 1] * inv0);
            *(unsigned*)(P + ((r0 + 8) * PK + 8 * nt + cb) * 2) =
                packbf(c[4 * nt + 2] * inv1, c[4 * nt + 3] * inv1);
        }
    }
    __syncthreads();   // P visible to all warps

    // ---- phase 2: pipelined over 8 chunks of d=16 ----
#pragma unroll
    for (int i = 0; i < 64; i++) c[i] = 0.f;

    const unsigned aS2     = ((wid * 16 + (lane & 15)) * PJ2 + ((lane >> 4) & 1) * 8) * 2;
    const unsigned aP_base = ((wid * 16 + (lane & 15)) * PK  + ((lane >> 4) & 1) * 8) * 2;
    const unsigned Psm     = smaddr(smem + OFF_P);

#pragma unroll 1
    for (int jc = 0; jc < NCH; ++jc) {
        if (jc == NCH - 1) asm volatile("cp.async.wait_group 0;" ::: "memory");
        else               asm volatile("cp.async.wait_group 1;" ::: "memory");
        __syncthreads();   // chunk jc visible to all threads

        const unsigned st = smaddr(smem) + (jc & 1) * STGSZ;
        unsigned aH[4], aL[4], aP[4];
        ldsm4(aH, st + C_SH + aS2);
        ldsm4(aL, st + C_SL + aS2);
        ldsm4(aP, Psm + aP_base + jc * CH * 2);
#pragma unroll
        for (int nb = 0; nb < 8; nb++) {
            const unsigned off = bOff + nb * 16 * 2;
            unsigned bW[4], bH[4], bL[4];
            ldsm4t(bW, st + C_W  + off);
            ldsm4t(bH, st + C_BH + off);
            ldsm4t(bL, st + C_BL + off);
            float* cc0 = c + 8 * nb;
            float* cc1 = c + 8 * nb + 4;
            mma16816(cc0, aP, bW);  mma16816(cc1, aP, bW + 2);
            mma16816(cc0, aH, bH);  mma16816(cc1, aH, bH + 2);
            mma16816(cc0, aH, bL);  mma16816(cc1, aH, bL + 2);
            mma16816(cc0, aL, bH);  mma16816(cc1, aL, bH + 2);
        }
        __syncthreads();   // stage (jc&1) free for reuse
        if (jc + 2 < NCH) ISSUE_CHUNK(jc + 2);
    }

    const int orow = i0 + wid * 16 + (lane >> 2);
    const int ocol = 2 * (lane & 3);
    float* outB = out + ((long long)b * SEQ + orow) * DIM;
#pragma unroll
    for (int nt = 0; nt < 16; nt++) {
        int colx = 8 * nt + ocol;
        float2 v01 = make_float2(lrelu(c[4 * nt + 0]), lrelu(c[4 * nt + 1]));
        float2 v23 = make_float2(lrelu(c[4 * nt + 2]), lrelu(c[4 * nt + 3]));
        *(float2*)(outB + colx)           = v01;
        *(float2*)(outB + 8 * DIM + colx) = v23;
    }
}

extern "C" void kernel_launch(void* const* d_in, const int* in_sizes, int n_in,
                              void* d_out, int out_size)
{
    (void)in_sizes; (void)n_in; (void)out_size;
    const float* nodes = (const float*)d_in[0];
    const int*   adj   = (const int*)d_in[1];
    const float* Wm    = (const float*)d_in[2];
    const float* Bm    = (const float*)d_in[3];
    float*       out   = (float*)d_out;

    cudaFuncSetAttribute(gcn_fused_kernel,
                         cudaFuncAttributeMaxDynamicSharedMemorySize, SMEM_SZ);

    prep_nodes<<<BATCHN * SEQ * DIM / (256 * 4), 256>>>(nodes);
    prep_params<<<32, 256>>>(Wm, Bm);
    dim3 grid(SEQ / 128, BATCHN);
    gcn_fused_kernel<<<grid, 256, SMEM_SZ>>>(adj, out);
}

// round 10
// speedup vs baseline: 1.6149x; 1.0876x over previous
#include <cuda_runtime.h>
#include <cuda_bf16.h>
#include <cstdint>

#define BATCHN 32
#define SEQ    1024
#define DIM    128
#define KC     32
#define NITER  (SEQ / KC)
#define PK     136

__device__ uint4 g_nbf4[BATCHN * SEQ * DIM / 8];
__device__ uint4 g_wbf4[DIM * DIM / 8];
__device__ uint4 g_bh4[DIM * DIM / 8];
__device__ uint4 g_bl4[DIM * DIM / 8];

// ---------------- helpers ----------------
__device__ __forceinline__ unsigned smaddr(const void* p) {
    return (unsigned)__cvta_generic_to_shared(p);
}
__device__ __forceinline__ void ldsm4(unsigned* r, unsigned a) {
    asm volatile("ldmatrix.sync.aligned.m8n8.x4.shared.b16 {%0,%1,%2,%3},[%4];"
                 : "=r"(r[0]), "=r"(r[1]), "=r"(r[2]), "=r"(r[3]) : "r"(a));
}
__device__ __forceinline__ void ldsm4t(unsigned* r, unsigned a) {
    asm volatile("ldmatrix.sync.aligned.m8n8.x4.trans.shared.b16 {%0,%1,%2,%3},[%4];"
                 : "=r"(r[0]), "=r"(r[1]), "=r"(r[2]), "=r"(r[3]) : "r"(a));
}
__device__ __forceinline__ void mma16816(float* c, const unsigned* a, const unsigned* b) {
    asm volatile("mma.sync.aligned.m16n8k16.row.col.f32.bf16.bf16.f32 "
                 "{%0,%1,%2,%3},{%4,%5,%6,%7},{%8,%9},{%0,%1,%2,%3};"
                 : "+f"(c[0]), "+f"(c[1]), "+f"(c[2]), "+f"(c[3])
                 : "r"(a[0]), "r"(a[1]), "r"(a[2]), "r"(a[3]), "r"(b[0]), "r"(b[1]));
}
__device__ __forceinline__ unsigned packbf(float lo, float hi) {
    unsigned r;
    asm("cvt.rn.bf16x2.f32 %0, %1, %2;" : "=r"(r) : "f"(hi), "f"(lo));
    return r;
}
__device__ __forceinline__ void cpa16(unsigned s, const void* g) {
    asm volatile("cp.async.cg.shared.global [%0], [%1], 16;" :: "r"(s), "l"(g) : "memory");
}
__device__ __forceinline__ void cp_commit() {
    asm volatile("cp.async.commit_group;" ::: "memory");
}
__device__ __forceinline__ float lrelu(float x) { return x >= 0.f ? x : 0.1f * x; }
__device__ __forceinline__ float bfh(float x) {
    return __bfloat162float(__float2bfloat16_rn(x));
}

// ---------------- prep kernels ----------------
__global__ void prep_nodes(const float* __restrict__ nodes) {
    long long i = ((long long)blockIdx.x * 256 + threadIdx.x) * 8;
    float4 v0 = *(const float4*)(nodes + i);
    float4 v1 = *(const float4*)(nodes + i + 4);
    uint4 hi = make_uint4(packbf(bfh(v0.x), bfh(v0.y)), packbf(bfh(v0.z), bfh(v0.w)),
                          packbf(bfh(v1.x), bfh(v1.y)), packbf(bfh(v1.z), bfh(v1.w)));
    *(uint4*)((__nv_bfloat16*)g_nbf4 + i) = hi;
}

__global__ void prep_params(const float* __restrict__ Wm, const float* __restrict__ Bm) {
    int q = blockIdx.x * 256 + threadIdx.x;
    if (q < 4096) {
        long long i = (long long)q * 4;
        float4 w = *(const float4*)(Wm + i);
        *(uint2*)((__nv_bfloat16*)g_wbf4 + i) = make_uint2(packbf(w.x, w.y), packbf(w.z, w.w));
    } else {
        long long i = (long long)(q - 4096) * 4;
        float4 v = *(const float4*)(Bm + i);
        float hx = bfh(v.x), hy = bfh(v.y), hz = bfh(v.z), hw = bfh(v.w);
        *(uint2*)((__nv_bfloat16*)g_bh4 + i) = make_uint2(packbf(hx, hy), packbf(hz, hw));
        *(uint2*)((__nv_bfloat16*)g_bl4 + i) =
            make_uint2(packbf(v.x - hx, v.y - hy), packbf(v.z - hz, v.w - hw));
    }
}

// smem map (bytes):
//  phase1: mask 2 stages @0 (17408) + nodes 4 stages @17408 (34816) -> [0, 52224)
//  P bf16 [128][PK] @52224 (34816)                                  -> [52224, 87040)
//  phase2: 2 chunk stages @0, each 25344 (W/Bh/Bl 16x272B, SH/SL 128x48B)
#define OFF_NODE 17408
#define OFF_P    52224
#define STGSZ    25344
#define C_W      0
#define C_BH     4352
#define C_BL     8704
#define C_SH     13056
#define C_SL     19200
#define CH       16
#define NCH      8
#define SMEM_SZ  87040

__global__ __launch_bounds__(256, 2)
void gcn_fused_kernel(const float* __restrict__ nodes, const int* __restrict__ adj,
                      float* __restrict__ out)
{
    extern __shared__ __align__(16) unsigned char smem[];
    __shared__ int scnt[128];

    const int t    = threadIdx.x;
    const int lane = t & 31;
    const int wid  = t >> 5;
    const int wm   = wid >> 1;     // 0..3 : owns 32 i-rows
    const int wn   = wid & 1;      // 0..1 : owns 64 d-cols
    const int b    = blockIdx.y;
    const int i0   = blockIdx.x * 128;

    if (t < 128) scnt[t] = 0;

    const int* adjBase = adj + (long long)b * SEQ * SEQ + i0 + 4 * lane;
    const __nv_bfloat16* nbfB = (const __nv_bfloat16*)g_nbf4 + (long long)b * SEQ * DIM;
    const __nv_bfloat16* wbf  = (const __nv_bfloat16*)g_wbf4;
    const __nv_bfloat16* bhp  = (const __nv_bfloat16*)g_bh4;
    const __nv_bfloat16* blp  = (const __nv_bfloat16*)g_bl4;

    const int ncRow0 = t >> 4,         ncCol0 = t & 15;
    const int ncRow1 = (t + 256) >> 4, ncCol1 = (t + 256) & 15;
    const unsigned nodeSm = smaddr(smem + OFF_NODE);
    const unsigned maskSm = smaddr(smem);

#define ISSUE_NODES(IT) do {                                                      \
        unsigned _sb = nodeSm + ((IT) & 3) * 8704;                                \
        const __nv_bfloat16* _g = nbfB + (IT) * KC * DIM;                         \
        cpa16(_sb + ncRow0 * 272 + ncCol0 * 16, _g + ncRow0 * DIM + ncCol0 * 8);  \
        cpa16(_sb + ncRow1 * 272 + ncCol1 * 16, _g + ncRow1 * DIM + ncCol1 * 8);  \
        cp_commit();                                                              \
    } while (0)

#define ISSUE_W(JC) do {                                                          \
        unsigned _st = maskSm + ((JC) & 1) * STGSZ;                               \
        int _r = t >> 4, _cc = t & 15;                                            \
        unsigned _so = _r * 272 + _cc * 16;                                       \
        int _go = ((JC) * CH + _r) * DIM + _cc * 8;                               \
        cpa16(_st + C_W  + _so, wbf + _go);                                      \
        cpa16(_st + C_BH + _so, bhp + _go);                                      \
        cpa16(_st + C_BL + _so, blp + _go);                                      \
        cp_commit();                                                              \
    } while (0)

#define STS_SELF(JC, VA, VB) do {                                                 \
        unsigned char* _p = smem + ((JC) & 1) * STGSZ;                            \
        float _h0 = bfh((VA).x), _h1 = bfh((VA).y), _h2 = bfh((VA).z), _h3 = bfh((VA).w); \
        float _h4 = bfh((VB).x), _h5 = bfh((VB).y), _h6 = bfh((VB).z), _h7 = bfh((VB).w); \
        *(uint4*)(_p + C_SH + (t >> 1) * 48 + (t & 1) * 16) =                     \
            make_uint4(packbf(_h0, _h1), packbf(_h2, _h3),                        \
                       packbf(_h4, _h5), packbf(_h6, _h7));                       \
        *(uint4*)(_p + C_SL + (t >> 1) * 48 + (t & 1) * 16) =                     \
            make_uint4(packbf((VA).x - _h0, (VA).y - _h1),                        \
                       packbf((VA).z - _h2, (VA).w - _h3),                        \
                       packbf((VB).x - _h4, (VB).y - _h5),                        \
                       packbf((VB).z - _h6, (VB).w - _h7));                       \
    } while (0)

    ISSUE_NODES(0);
    ISSUE_NODES(1);

    int4 mreg[4];
#pragma unroll
    for (int p = 0; p < 4; p++)
        mreg[p] = *(const int4*)(adjBase + (long long)(wid + 8 * p) * SEQ);

    float c[64];
#pragma unroll
    for (int i = 0; i < 64; i++) c[i] = 0.f;
    int cnt0 = 0, cnt1 = 0, cnt2 = 0, cnt3 = 0;

    // ldmatrix offsets
    const unsigned aRow  = (lane & 7) + ((lane >> 4) & 1) * 8;   // o within 16
    const unsigned aCol8 = ((lane >> 3) & 1) * 8;                // i 8-offset
    const unsigned bRow  = (lane & 7) + ((lane >> 3) & 1) * 8;   // o/k within 16
    const unsigned bCol8 = ((lane >> 4) & 1) * 8;                // d 8-offset
    const unsigned bOff  = (bRow * PK + bCol8) * 2;

    for (int it = 0; it < NITER; ++it) {
        unsigned mst = (it & 1) * 8704;
#pragma unroll
        for (int p = 0; p < 4; p++) {
            int o = wid + 8 * p;
            int4 m = mreg[p];
            cnt0 += (m.x != 0); cnt1 += (m.y != 0); cnt2 += (m.z != 0); cnt3 += (m.w != 0);
            unsigned lo = (m.x ? 0x3F80u : 0u) | (m.y ? 0x3F800000u : 0u);
            unsigned hi = (m.z ? 0x3F80u : 0u) | (m.w ? 0x3F800000u : 0u);
            *(uint2*)(smem + mst + (o * PK + 4 * lane) * 2) = make_uint2(lo, hi);
        }
        if (it + 1 < NITER) {
            const int* ab = adjBase + (long long)(it + 1) * KC * SEQ;
#pragma unroll
            for (int p = 0; p < 4; p++)
                mreg[p] = *(const int4*)(ab + (long long)(wid + 8 * p) * SEQ);
        }
        {
            int nx = it + 2;
            if (nx >= NITER) nx -= NITER;   // dead wrap keeps group FIFO uniform
            ISSUE_NODES(nx);
        }
        asm volatile("cp.async.wait_group 2;" ::: "memory");
        __syncthreads();

        const unsigned mA = maskSm + (it & 1) * 8704;
        const unsigned nB = nodeSm + (it & 3) * 8704;
#pragma unroll
        for (int kk = 0; kk < 2; kk++) {
            unsigned a0[4], a1[4];
            ldsm4t(a0, mA + ((kk * 16 + aRow) * PK + wm * 32 + aCol8) * 2);
            ldsm4t(a1, mA + ((kk * 16 + aRow) * PK + wm * 32 + 16 + aCol8) * 2);
#pragma unroll
            for (int ng = 0; ng < 4; ng++) {
                unsigned bb[4];
                ldsm4t(bb, nB + ((kk * 16 + bRow) * PK + wn * 64 + ng * 16 + bCol8) * 2);
                mma16816(c + (2 * ng + 0) * 4,     a0, bb);
                mma16816(c + (2 * ng + 1) * 4,     a0, bb + 2);
                mma16816(c + (8 + 2 * ng + 0) * 4, a1, bb);
                mma16816(c + (8 + 2 * ng + 1) * 4, a1, bb + 2);
            }
        }
    }

    atomicAdd(&scnt[4 * lane + 0], cnt0);
    atomicAdd(&scnt[4 * lane + 1], cnt1);
    atomicAdd(&scnt[4 * lane + 2], cnt2);
    atomicAdd(&scnt[4 * lane + 3], cnt3);
    // drain wrapped dead node groups: phase-2 stages reuse this smem
    asm volatile("cp.async.wait_group 0;" ::: "memory");
    __syncthreads();   // scnt valid; phase-1 smem dead

    // --- phase-2 prologue: overlap loads with P normalize/store ---
    const float* selfF = nodes + ((long long)b * SEQ + i0 + (t >> 1)) * DIM + (t & 1) * 8;
    float4 s0a = *(const float4*)(selfF + 0);
    float4 s0b = *(const float4*)(selfF + 4);
    float4 s1a = *(const float4*)(selfF + 16);
    float4 s1b = *(const float4*)(selfF + 20);
    ISSUE_W(0);
    ISSUE_W(1);

    // normalize P (2D fragment layout) and store bf16 to P region
    {
        const int rBase = wm * 32 + (lane >> 2);
        const float i00 = 1.f / fmaxf((float)scnt[rBase], 1.f);
        const float i01 = 1.f / fmaxf((float)scnt[rBase + 8], 1.f);
        const float i10 = 1.f / fmaxf((float)scnt[rBase + 16], 1.f);
        const float i11 = 1.f / fmaxf((float)scnt[rBase + 24], 1.f);
        unsigned char* P = smem + OFF_P;
        const int colB = wn * 64 + 2 * (lane & 3);
#pragma unroll
        for (int mt = 0; mt < 2; mt++) {
            const float ivA = mt ? i10 : i00;
            const float ivB = mt ? i11 : i01;
            const int r0 = rBase + mt * 16;
#pragma unroll
            for (int nn = 0; nn < 8; nn++) {
                float* cc = c + (mt * 8 + nn) * 4;
                const int col = colB + nn * 8;
                *(unsigned*)(P + (r0 * PK + col) * 2)       = packbf(cc[0] * ivA, cc[1] * ivA);
                *(unsigned*)(P + ((r0 + 8) * PK + col) * 2) = packbf(cc[2] * ivB, cc[3] * ivB);
            }
        }
    }
    STS_SELF(0, s0a, s0b);
    STS_SELF(1, s1a, s1b);

    // ---- phase 2: out = P@W + selfH@Bh + selfH@Bl + selfL@Bh ----
#pragma unroll
    for (int i = 0; i < 64; i++) c[i] = 0.f;

    const unsigned aS2     = ((wid * 16 + (lane & 15)) * 24 + ((lane >> 4) & 1) * 8) * 2;
    const unsigned aP_base = ((wid * 16 + (lane & 15)) * PK + ((lane >> 4) & 1) * 8) * 2;
    const unsigned Psm = maskSm + OFF_P;

    float4 pa, pb;
#pragma unroll 1
    for (int jc = 0; jc < NCH; ++jc) {
        if (jc == NCH - 1) asm volatile("cp.async.wait_group 0;" ::: "memory");
        else               asm volatile("cp.async.wait_group 1;" ::: "memory");
        __syncthreads();   // chunk jc (cp.async + self STS) visible

        if (jc + 2 < NCH) {
            pa = *(const float4*)(selfF + (jc + 2) * CH);
            pb = *(const float4*)(selfF + (jc + 2) * CH + 4);
        }

        const unsigned st = maskSm + (jc & 1) * STGSZ;
        unsigned aH[4], aL[4], aP[4];
        ldsm4(aH, st + C_SH + aS2);
        ldsm4(aL, st + C_SL + aS2);
        ldsm4(aP, Psm + aP_base + jc * CH * 2);
#pragma unroll
        for (int nb = 0; nb < 8; nb++) {
            const unsigned off = bOff + nb * 16 * 2;
            unsigned bW[4], bH[4], bL[4];
            ldsm4t(bW, st + C_W  + off);
            ldsm4t(bH, st + C_BH + off);
            ldsm4t(bL, st + C_BL + off);
            float* cc0 = c + 8 * nb;
            float* cc1 = c + 8 * nb + 4;
            mma16816(cc0, aP, bW);  mma16816(cc1, aP, bW + 2);
            mma16816(cc0, aH, bH);  mma16816(cc1, aH, bH + 2);
            mma16816(cc0, aH, bL);  mma16816(cc1, aH, bL + 2);
            mma16816(cc0, aL, bH);  mma16816(cc1, aL, bH + 2);
        }
        __syncthreads();   // stage (jc&1) free for reuse
        if (jc + 2 < NCH) {
            ISSUE_W(jc + 2);
            STS_SELF(jc + 2, pa, pb);
        }
    }

    const int orow = i0 + wid * 16 + (lane >> 2);
    const int ocol = 2 * (lane & 3);
    float* outB = out + ((long long)b * SEQ + orow) * DIM;
#pragma unroll
    for (int nt = 0; nt < 16; nt++) {
        int colx = 8 * nt + ocol;
        float2 v01 = make_float2(lrelu(c[4 * nt + 0]), lrelu(c[4 * nt + 1]));
        float2 v23 = make_float2(lrelu(c[4 * nt + 2]), lrelu(c[4 * nt + 3]));
        *(float2*)(outB + colx)           = v01;
        *(float2*)(outB + 8 * DIM + colx) = v23;
    }
}

extern "C" void kernel_launch(void* const* d_in, const int* in_sizes, int n_in,
                              void* d_out, int out_size)
{
    (void)in_sizes; (void)n_in; (void)out_size;
    const float* nodes = (const float*)d_in[0];
    const int*   adj   = (const int*)d_in[1];
    const float* Wm    = (const float*)d_in[2];
    const float* Bm    = (const float*)d_in[3];
    float*       out   = (float*)d_out;

    cudaFuncSetAttribute(gcn_fused_kernel,
                         cudaFuncAttributeMaxDynamicSharedMemorySize, SMEM_SZ);

    prep_nodes<<<BATCHN * SEQ * DIM / (256 * 8), 256>>>(nodes);
    prep_params<<<32, 256>>>(Wm, Bm);
    dim3 grid(SEQ / 128, BATCHN);
    gcn_fused_kernel<<<grid, 256, SMEM_SZ>>>(nodes, adj, out);
}